// round 10
// baseline (speedup 1.0000x reference)
#include <cuda_runtime.h>
#include <cstdint>
#include <math.h>

#define NROWS 16384
#define DIN   64
#define HDIM  256
#define LOUT  64
#define NEXP  256
#define TM    64
#define MAXT  (NROWS / TM + NEXP)

#define SX  68    // Xs row stride (floats)
#define SW  68    // W slab row stride
#define SH  264   // H row stride (8 mod 32 -> conflict-free v2 A loads)
#define SWL 260   // Wl row stride

#define NTHREADS 512

// ---- scratch ----
__device__ int g_cnt[NEXP];
__device__ int g_cur[NEXP];
__device__ int g_sorted[NROWS];
__device__ int g_te[MAXT];
__device__ int g_tr0[MAXT];
__device__ int g_trn[MAXT];

// ---------------- sort/plan ----------------
__global__ void k_hist(const int* __restrict__ ind) {
    int n = blockIdx.x * blockDim.x + threadIdx.x;
    atomicAdd(&g_cnt[ind[n]], 1);
}

__global__ void k_plan() {
    __shared__ int sc[NEXP];
    int t = threadIdx.x;
    int c = g_cnt[t];
    g_cnt[t] = 0;                       // re-zero for next graph replay
    sc[t] = c; __syncthreads();
    for (int s = 1; s < NEXP; s <<= 1) {
        int v = (t >= s) ? sc[t - s] : 0;
        __syncthreads(); sc[t] += v; __syncthreads();
    }
    int off = sc[t] - c;
    g_cur[t] = off;
    int nt = (c + TM - 1) / TM;
    __syncthreads();
    sc[t] = nt; __syncthreads();
    for (int s = 1; s < NEXP; s <<= 1) {
        int v = (t >= s) ? sc[t - s] : 0;
        __syncthreads(); sc[t] += v; __syncthreads();
    }
    int tb = sc[t] - nt;
    for (int i = t; i < MAXT; i += NEXP) g_trn[i] = 0;
    __syncthreads();
    for (int j = 0; j < nt; j++) {
        g_te[tb + j]  = t;
        g_tr0[tb + j] = off + j * TM;
        g_trn[tb + j] = min(TM, c - j * TM);
    }
}

__global__ void k_scatter(const int* __restrict__ ind) {
    int n = blockIdx.x * blockDim.x + threadIdx.x;
    int e = ind[n];
    int p = atomicAdd(&g_cur[e], 1);
    g_sorted[p] = n;
}

// ---------------- helpers (sm_80-baseline PTX only) ----------------
static __device__ __forceinline__ uint32_t f2tf(float f) {
    uint32_t r; asm("cvt.rna.tf32.f32 %0, %1;" : "=r"(r) : "f"(f)); return r;
}
static __device__ __forceinline__ void mma8(float* c, const uint32_t* a, const uint32_t* b) {
    asm("mma.sync.aligned.m16n8k8.row.col.f32.tf32.tf32.f32 "
        "{%0,%1,%2,%3}, {%4,%5,%6,%7}, {%8,%9}, {%0,%1,%2,%3};"
        : "+f"(c[0]), "+f"(c[1]), "+f"(c[2]), "+f"(c[3])
        : "r"(a[0]), "r"(a[1]), "r"(a[2]), "r"(a[3]), "r"(b[0]), "r"(b[1]));
}
static __device__ __forceinline__ void cp16(uint32_t dst, const float* src) {
    asm volatile("cp.async.cg.shared.global [%0], [%1], 16;" :: "r"(dst), "l"(src));
}
#define CP_COMMIT() asm volatile("cp.async.commit_group;")
#define CP_WAIT0()  asm volatile("cp.async.wait_group 0;")
#define CP_WAIT1()  asm volatile("cp.async.wait_group 1;")

static __device__ __forceinline__ float mytanh(float x) {
    float xc = fminf(fmaxf(x, -15.f), 15.f);
    float e = __expf(2.f * xc);
    return __fdividef(e - 1.f, e + 1.f);
}

// ---------------- SMEM map (floats) ----------------
#define OXS   0                     // 64 x 68   = 4352
#define OH    4352                  // 64 x 264  = 16896
#define OWA   21248                 // 256 x 68  = 17408
#define OWB   38656                 // 256 x 68  = 17408
#define OROWS 56064                 // 64 ints
#define SMEM_FLOATS 56128
#define SMEM_BYTES  (SMEM_FLOATS * 4)

static __device__ __forceinline__ void cp_w2slab(const float* __restrict__ W2e, int kt,
                                                 uint32_t ubuf, int tid) {
    #pragma unroll
    for (int i = 0; i < 8; i++) {
        int c = tid + i * NTHREADS; int r = c >> 4, kc = (c & 15) << 2;
        cp16(ubuf + (r * SW + kc) * 4, W2e + r * HDIM + kt * 64 + kc);
    }
}

// Stage-2-style 64-k block: A = permuted/pre-rounded H (v2, no cvt), B = weight slab.
// Warp w computes o-cols [w*16, w*16+16), all 64 m-rows. acc[4][2][4].
static __device__ __forceinline__ void mm64p(const float* __restrict__ A, // + kt*64 col base
                                             const float* __restrict__ B,
                                             int g, int t, int w,
                                             float acc[4][2][4]) {
    #pragma unroll
    for (int kk = 0; kk < 8; kk++) {
        int kc = kk * 8 + 2 * t;
        uint32_t a[4][4];
        #pragma unroll
        for (int mt = 0; mt < 4; mt++) {
            int row = mt * 16 + g;
            float2 lo = *(const float2*)&A[row * SH + kc];
            float2 hi = *(const float2*)&A[(row + 8) * SH + kc];
            a[mt][0] = __float_as_uint(lo.x); a[mt][1] = __float_as_uint(hi.x);
            a[mt][2] = __float_as_uint(lo.y); a[mt][3] = __float_as_uint(hi.y);
        }
        uint32_t b[2][2];
        #pragma unroll
        for (int ot = 0; ot < 2; ot++) {
            const float* p = B + (w * 16 + ot * 8 + g) * SW + kk * 8 + t;
            b[ot][0] = f2tf(p[0]); b[ot][1] = f2tf(p[4]);
        }
        #pragma unroll
        for (int mt = 0; mt < 4; mt++)
            #pragma unroll
            for (int ot = 0; ot < 2; ot++)
                mma8(acc[mt][ot], a[mt], b[ot]);
    }
}

// Epilogue: bias+tanh, store pre-rounded tf32 bits into permuted-k H layout.
// pair (col=base+2t, base+2t+1) -> positions p0 = base + ((t&1)<<2)+(t>>1), p0+2.
static __device__ __forceinline__ void epi_store(float* __restrict__ H_,
                                                 const float* __restrict__ bias,
                                                 int g, int t, int w,
                                                 float acc[4][2][4]) {
    #pragma unroll
    for (int ot = 0; ot < 2; ot++) {
        int base = w * 16 + ot * 8;
        int col  = base + 2 * t;
        float2 bb = *(const float2*)(bias + col);
        int p0 = base + ((t & 1) << 2) + (t >> 1);
        #pragma unroll
        for (int mt = 0; mt < 4; mt++) {
            int r0 = mt * 16 + g, r1 = r0 + 8;
            H_[r0 * SH + p0]     = __uint_as_float(f2tf(mytanh(acc[mt][ot][0] + bb.x)));
            H_[r0 * SH + p0 + 2] = __uint_as_float(f2tf(mytanh(acc[mt][ot][1] + bb.y)));
            H_[r1 * SH + p0]     = __uint_as_float(f2tf(mytanh(acc[mt][ot][2] + bb.x)));
            H_[r1 * SH + p0 + 2] = __uint_as_float(f2tf(mytanh(acc[mt][ot][3] + bb.y)));
            acc[mt][ot][0] = 0.f; acc[mt][ot][1] = 0.f;
            acc[mt][ot][2] = 0.f; acc[mt][ot][3] = 0.f;
        }
    }
}

// ---------------- main kernel ----------------
__global__ __launch_bounds__(NTHREADS, 1)
void k_mlp(const float* __restrict__ x,
           const float* __restrict__ W1, const float* __restrict__ b1,
           const float* __restrict__ W2, const float* __restrict__ b2,
           const float* __restrict__ Wl, const float* __restrict__ bl,
           float* __restrict__ out)
{
    int bid = blockIdx.x;
    int M = g_trn[bid];
    if (M == 0) return;
    int e  = g_te[bid];
    int r0 = g_tr0[bid];

    extern __shared__ float sm[];
    float* Xs = sm + OXS;
    float* H  = sm + OH;
    float* WA = sm + OWA;
    float* WB = sm + OWB;
    int* rows = (int*)(sm + OROWS);
    uint32_t sb = (uint32_t)__cvta_generic_to_shared(sm);
    uint32_t uXS = sb + OXS * 4, uWA = sb + OWA * 4, uWB = sb + OWB * 4;

    int tid = threadIdx.x;
    int w = tid >> 5, lane = tid & 31, g = lane >> 2, t = lane & 3;

    const float* W1e = W1 + (size_t)e * HDIM * DIN;
    const float* W2e = W2 + (size_t)e * HDIM * HDIM;
    const float* Wle = Wl + (size_t)e * LOUT * HDIM;

    // ---- P0: X + W1 (group0), W2 slab0 (group1) ----
    #pragma unroll
    for (int i = 0; i < 2; i++) {
        int c = tid + i * NTHREADS;
        int m = c >> 4, kc = (c & 15) << 2;
        int row = g_sorted[r0 + ((m < M) ? m : (M - 1))];
        cp16(uXS + (m * SX + kc) * 4, x + (size_t)row * DIN + kc);
    }
    #pragma unroll
    for (int i = 0; i < 8; i++) {
        int c = tid + i * NTHREADS; int r = c >> 4, kc = (c & 15) << 2;
        cp16(uWA + (r * SW + kc) * 4, W1e + r * DIN + kc);
    }
    CP_COMMIT();
    cp_w2slab(W2e, 0, uWB, tid);
    CP_COMMIT();

    if (tid < TM) rows[tid] = g_sorted[r0 + ((tid < M) ? tid : (M - 1))];

    float acc[4][2][4];
    #pragma unroll
    for (int mt = 0; mt < 4; mt++)
        #pragma unroll
        for (int ot = 0; ot < 2; ot++)
            #pragma unroll
            for (int i = 0; i < 4; i++) acc[mt][ot][i] = 0.f;

    CP_WAIT0();
    __syncthreads();

    // ================= stage 1: H1 = tanh(X @ W1^T + b1) =================
    // A = Xs (unpermuted, needs cvt), B = W1 in WA.
    #pragma unroll
    for (int kk = 0; kk < 8; kk++) {
        int k0 = kk * 8;
        uint32_t a[4][4];
        #pragma unroll
        for (int mt = 0; mt < 4; mt++) {
            const float* p = Xs + (mt * 16 + g) * SX + k0 + t;
            a[mt][0] = f2tf(p[0]);          a[mt][1] = f2tf(p[8 * SX]);
            a[mt][2] = f2tf(p[4]);          a[mt][3] = f2tf(p[8 * SX + 4]);
        }
        uint32_t b[2][2];
        #pragma unroll
        for (int ot = 0; ot < 2; ot++) {
            const float* p = WA + (w * 16 + ot * 8 + g) * SW + k0 + t;
            b[ot][0] = f2tf(p[0]);          b[ot][1] = f2tf(p[4]);
        }
        #pragma unroll
        for (int mt = 0; mt < 4; mt++)
            #pragma unroll
            for (int ot = 0; ot < 2; ot++)
                mma8(acc[mt][ot], a[mt], b[ot]);
    }
    __syncthreads();                 // WA free

    cp_w2slab(W2e, 1, uWA, tid);     // slab1 -> WA, overlaps epilogue + kt0
    CP_COMMIT();

    epi_store(H, b1 + e * HDIM, g, t, w, acc);   // epilogue 1 (pre-rounded, permuted)
    __syncthreads();                 // H1 visible; WB(slab0) arrived at P0 wait

    // ================= stage 2: H2 = tanh(H1 @ W2^T + b2) =================
    #pragma unroll 1
    for (int kt = 0; kt < 4; kt++) {
        const float* Wc = (kt & 1) ? WA : WB;
        uint32_t uWc = (kt & 1) ? uWA : uWB;
        mm64p(H + kt * 64, Wc, g, t, w, acc);
        __syncthreads();             // this buffer free
        if (kt < 2) {
            cp_w2slab(W2e, kt + 2, uWc, tid);
            CP_COMMIT(); CP_WAIT1(); __syncthreads();
        } else if (kt == 2) {
            #pragma unroll            // Wl -> WB (64 x 256, stride SWL)
            for (int i = 0; i < 8; i++) {
                int c = tid + i * NTHREADS; int r = c >> 6, kc = (c & 63) << 2;
                cp16(uWB + (r * SWL + kc) * 4, Wle + r * HDIM + kc);
            }
            CP_COMMIT(); CP_WAIT1(); __syncthreads();
        }
    }

    epi_store(H, b2 + e * HDIM, g, t, w, acc);   // epilogue 2 (H2 overwrites H1)
    CP_WAIT0();                      // Wl arrived
    __syncthreads();                 // H2 + Wl visible

    // ================= stage 3: out = H2 @ Wl^T + bl =================
    {
        int og = w & 7, mg = w >> 3;           // 8 o-groups x 2 m-groups
        float a3[2][4];
        #pragma unroll
        for (int mt = 0; mt < 2; mt++)
            #pragma unroll
            for (int i = 0; i < 4; i++) a3[mt][i] = 0.f;

        #pragma unroll
        for (int kk = 0; kk < 32; kk++) {
            int kc = kk * 8 + 2 * t;
            uint32_t a[2][4];
            #pragma unroll
            for (int mt = 0; mt < 2; mt++) {
                int row = mg * 32 + mt * 16 + g;
                float2 lo = *(const float2*)&H[row * SH + kc];
                float2 hi = *(const float2*)&H[(row + 8) * SH + kc];
                a[mt][0] = __float_as_uint(lo.x); a[mt][1] = __float_as_uint(hi.x);
                a[mt][2] = __float_as_uint(lo.y); a[mt][3] = __float_as_uint(hi.y);
            }
            uint32_t b[2];
            {
                const float* p = WB + (og * 8 + g) * SWL + kk * 8 + t;
                b[0] = f2tf(p[0]);  b[1] = f2tf(p[4]);
            }
            #pragma unroll
            for (int mt = 0; mt < 2; mt++)
                mma8(a3[mt], a[mt], b);
        }

        int col = og * 8 + 2 * t;
        float2 bb = *(const float2*)(bl + e * LOUT + col);
        #pragma unroll
        for (int mt = 0; mt < 2; mt++) {
            int m0g = mg * 32 + mt * 16 + g;
            if (m0g < M) {
                float2 v; v.x = a3[mt][0] + bb.x; v.y = a3[mt][1] + bb.y;
                *(float2*)&out[(size_t)rows[m0g] * LOUT + col] = v;
            }
            if (m0g + 8 < M) {
                float2 v; v.x = a3[mt][2] + bb.x; v.y = a3[mt][3] + bb.y;
                *(float2*)&out[(size_t)rows[m0g + 8] * LOUT + col] = v;
            }
        }
    }
}

// ---------------- launch ----------------
extern "C" void kernel_launch(void* const* d_in, const int* in_sizes, int n_in,
                              void* d_out, int out_size) {
    (void)in_sizes; (void)n_in; (void)out_size;
    const float* x  = (const float*)d_in[0];
    const int*   nd = (const int*)  d_in[1];
    const float* W1 = (const float*)d_in[2];
    const float* b1 = (const float*)d_in[3];
    const float* W2 = (const float*)d_in[4];
    const float* b2 = (const float*)d_in[5];
    const float* Wl = (const float*)d_in[6];
    const float* bl = (const float*)d_in[7];
    float* out = (float*)d_out;

    cudaFuncSetAttribute(k_mlp, cudaFuncAttributeMaxDynamicSharedMemorySize, SMEM_BYTES);

    k_hist<<<NROWS / 256, 256>>>(nd);
    k_plan<<<1, NEXP>>>();
    k_scatter<<<NROWS / 256, 256>>>(nd);
    k_mlp<<<MAXT, NTHREADS, SMEM_BYTES>>>(x, W1, b1, W2, b2, Wl, bl, out);
}